// round 14
// baseline (speedup 1.0000x reference)
#include <cuda_runtime.h>

#define NMAX 50000
#define ACC4 (NMAX * 3)

// ---- scratch (static __device__, zero-initialized at module load) ----
// Invariants at entry of every kernel_launch: g_accum == 0, g_easum == 0, g_done == 0.
__device__ float4   g_accum[ACC4];   // per node: [denom(4)][T0(4)][T1(4)]
__device__ float    g_consts[20];    // s0[4] s1[4] d0[4] d1[4] g[4]
__device__ float    g_easum;
__device__ unsigned g_done;

struct C20 { float s0[4], s1[4], d0[4], d1[4], g[4]; };

// Per-block inline computation of the 20 head constants (shared reduction).
__device__ __forceinline__ void block_consts(const float* __restrict__ W,
                                             const float* __restrict__ att_src,
                                             const float* __restrict__ att_dst,
                                             const float* __restrict__ W_edge,
                                             const float* __restrict__ att_edge,
                                             float* cs /*shared[20]*/) {
    __shared__ float sh[5][256];
    int t = threadIdx.x;          // 256 threads = H*C
    int h = t >> 6;
    float w0 = __ldg(&W[2 * t]), w1 = __ldg(&W[2 * t + 1]);
    float as = __ldg(&att_src[t]), ad = __ldg(&att_dst[t]);
    sh[0][t] = w0 * as;
    sh[1][t] = w1 * as;
    sh[2][t] = w0 * ad;
    sh[3][t] = w1 * ad;
    sh[4][t] = __ldg(&W_edge[t]) * __ldg(&att_edge[t]);
    __syncthreads();
    for (int off = 32; off >= 1; off >>= 1) {
        if ((t & 63) < off) {
            #pragma unroll
            for (int k = 0; k < 5; k++) sh[k][t] += sh[k][t + off];
        }
        __syncthreads();
    }
    if ((t & 63) == 0) {
        #pragma unroll
        for (int k = 0; k < 5; k++) cs[k * 4 + h] = sh[k][t];
    }
    __syncthreads();
}

__device__ __forceinline__ void red_v4(float4* p, float a, float b, float c, float d) {
    asm volatile("red.global.add.v4.f32 [%0], {%1,%2,%3,%4};"
                 :: "l"(p), "f"(a), "f"(b), "f"(c), "f"(d) : "memory");
}

__device__ __forceinline__ void edge_body(const float2* __restrict__ x2,
                                          int src, int dst, float w, int N, const C20& c) {
    if ((unsigned)src >= (unsigned)N || (unsigned)dst >= (unsigned)N) return;
    float2 xs = __ldg(&x2[src]);
    float2 xd = __ldg(&x2[dst]);
    float a0 = xs.x * c.s0[0] + xs.y * c.s1[0] + xd.x * c.d0[0] + xd.y * c.d1[0] + w * c.g[0];
    float a1 = xs.x * c.s0[1] + xs.y * c.s1[1] + xd.x * c.d0[1] + xd.y * c.d1[1] + w * c.g[1];
    float a2 = xs.x * c.s0[2] + xs.y * c.s1[2] + xd.x * c.d0[2] + xd.y * c.d1[2] + w * c.g[2];
    float a3 = xs.x * c.s0[3] + xs.y * c.s1[3] + xd.x * c.d0[3] + xd.y * c.d1[3] + w * c.g[3];
    a0 = fmaxf(a0, 0.2f * a0);
    a1 = fmaxf(a1, 0.2f * a1);
    a2 = fmaxf(a2, 0.2f * a2);
    a3 = fmaxf(a3, 0.2f * a3);
    float e0 = __expf(a0), e1 = __expf(a1), e2 = __expf(a2), e3 = __expf(a3);
    float4* base = &g_accum[dst * 3];
    red_v4(base,     e0,        e1,        e2,        e3);
    red_v4(base + 1, e0 * xs.x, e1 * xs.x, e2 * xs.x, e3 * xs.x);
    red_v4(base + 2, e0 * xs.y, e1 * xs.y, e2 * xs.y, e3 * xs.y);
}

// K1: edge pass (R9 form: 2 edges/thread, scalar streaming loads). UNCHANGED.
__global__ void k_edge(const int* __restrict__ ei, const float* __restrict__ ea,
                       const float* __restrict__ x,
                       const float* __restrict__ W, const float* __restrict__ att_src,
                       const float* __restrict__ att_dst, const float* __restrict__ W_edge,
                       const float* __restrict__ att_edge, int E, int N) {
    __shared__ float cs[20];
    block_consts(W, att_src, att_dst, W_edge, att_edge, cs);
    if (blockIdx.x == 0 && threadIdx.x < 20) g_consts[threadIdx.x] = cs[threadIdx.x];

    C20 c;
    #pragma unroll
    for (int h = 0; h < 4; h++) {
        c.s0[h] = cs[h];      c.s1[h] = cs[4 + h];
        c.d0[h] = cs[8 + h];  c.d1[h] = cs[12 + h];
        c.g[h]  = cs[16 + h];
    }
    const float2* x2 = (const float2*)x;
    int base = blockIdx.x * (blockDim.x * 2) + threadIdx.x;
    int e0 = base, e1 = base + blockDim.x;
    float wsum = 0.f;

    int s0 = 0, d0 = 0, s1 = 0, d1 = 0;
    float w0 = 0.f, w1 = 0.f;
    bool v0 = e0 < E, v1 = e1 < E;
    if (v0) { s0 = __ldcs(&ei[e0]); d0 = __ldcs(&ei[E + e0]); w0 = __ldcs(&ea[e0]); }
    if (v1) { s1 = __ldcs(&ei[e1]); d1 = __ldcs(&ei[E + e1]); w1 = __ldcs(&ea[e1]); }
    if (v0) { wsum += w0; edge_body(x2, s0, d0, w0, N, c); }
    if (v1) { wsum += w1; edge_body(x2, s1, d1, w1, N, c); }

    #pragma unroll
    for (int o = 16; o; o >>= 1) wsum += __shfl_down_sync(0xffffffffu, wsum, o);
    __shared__ float shw[8];
    if ((threadIdx.x & 31) == 0) shw[threadIdx.x >> 5] = wsum;
    __syncthreads();
    if (threadIdx.x == 0) {
        float s = 0.f;
        #pragma unroll
        for (int i = 0; i < 8; i++) s += shw[i];
        atomicAdd(&g_easum, s);
    }
}

// K2: warp-autonomous expansion — NO shared memory, NO barriers in hot path.
// Block covers 64 nodes. Warp w (lane l):
//   row   = w>>1           (node row class: rows row, row+4, ..., row+60)
//   h_bas = (w&1)*2        (this warp's 2 heads; sibling warp covers the other 2)
//   lane l owns (node = base+row+4*(l&15), head = h_bas+(l>>4)): loads its 3
//   accumulator scalars + x, computes T=(T0,T1), resets what it read.
// Store loop i=0..15: T fetched via 2 shfl from lane (l&16)|i; coalesced STG.128.
__global__ void k_out(const float* __restrict__ W, const float* __restrict__ bias,
                      const float* __restrict__ x, float* __restrict__ out,
                      int N, float invE) {
    int t = threadIdx.x;
    int lane = t & 31;
    int base = blockIdx.x * 64;
    int row  = (t >> 5) >> 1;            // warp>>1: 0..3
    int sub  = t & 63;                    // output float4 column (consistent: (w&1)*32+lane)
    int hB   = sub >> 4;                  // head for this thread's output columns

    // --- per-lane T computation (phase A, warp-local) ---
    int myNode = base + row + 4 * (lane & 15);
    int myH    = ((t >> 5) & 1) * 2 + (lane >> 4);
    float Tx = 0.f, Ty = 0.f;
    if (myNode < N) {
        float mg = g_easum * invE;
        float2 xn = ((const float2*)x)[myNode];
        float* acc = (float*)&g_accum[myNode * 3];
        float dd = __ldcg(&acc[myH]);
        float t0 = __ldcg(&acc[4 + myH]);
        float t1 = __ldcg(&acc[8 + myH]);
        acc[myH] = 0.f;                   // reset exactly what this lane read
        acc[4 + myH] = 0.f;
        acc[8 + myH] = 0.f;

        float c0 = g_consts[myH] + g_consts[8 + myH];
        float c1 = g_consts[4 + myH] + g_consts[12 + myH];
        float a = xn.x * c0 + xn.y * c1 + mg * g_consts[16 + myH];
        a = fmaxf(a, 0.2f * a);
        float ws = __expf(a);
        float r = 1.0f / (dd + ws);
        Tx = (t0 + ws * xn.x) * r;
        Ty = (t1 + ws * xn.y) * r;
    }

    // --- per-thread weights for output columns [sub*4 .. sub*4+3] ---
    const float4* W4 = (const float4*)W;
    float4 wa = __ldg(&W4[sub * 2]);
    float4 wb = __ldg(&W4[sub * 2 + 1]);
    float4 b4 = __ldg(&((const float4*)bias)[sub]);

    float4* o4 = (float4*)out;
    int srcHalf = lane & 16;

    if (base + 64 <= N) {
        #pragma unroll 4
        for (int i = 0; i < 16; i++) {
            float tx = __shfl_sync(0xffffffffu, Tx, srcHalf | i);
            float ty = __shfl_sync(0xffffffffu, Ty, srcHalf | i);
            float4 o;
            o.x = tx * wa.x + ty * wa.y + b4.x;
            o.y = tx * wa.z + ty * wa.w + b4.y;
            o.z = tx * wb.x + ty * wb.y + b4.z;
            o.w = tx * wb.z + ty * wb.w + b4.w;
            o4[(size_t)(base + row + 4 * i) * 64 + sub] = o;
        }
    } else {
        for (int i = 0; i < 16; i++) {
            float tx = __shfl_sync(0xffffffffu, Tx, srcHalf | i);
            float ty = __shfl_sync(0xffffffffu, Ty, srcHalf | i);
            int n = base + row + 4 * i;
            if (n < N) {
                float4 o;
                o.x = tx * wa.x + ty * wa.y + b4.x;
                o.y = tx * wa.z + ty * wa.w + b4.y;
                o.z = tx * wb.x + ty * wb.y + b4.z;
                o.w = tx * wb.z + ty * wb.w + b4.w;
                o4[(size_t)n * 64 + sub] = o;
            }
        }
    }

    // last block resets g_easum for next replay (all warps of this block have
    // read g_easum before this barrier; counter wraps g_done back to 0)
    __syncthreads();
    if (t == 0) {
        unsigned v = atomicInc(&g_done, gridDim.x - 1);
        if (v == gridDim.x - 1) g_easum = 0.f;
    }
}

extern "C" void kernel_launch(void* const* d_in, const int* in_sizes, int n_in,
                              void* d_out, int out_size) {
    const float* x        = (const float*)d_in[0];
    const int*   ei       = (const int*)d_in[1];     // int32 (JAX x64 off)
    const float* ea       = (const float*)d_in[2];
    const float* W        = (const float*)d_in[3];
    const float* att_src  = (const float*)d_in[4];
    const float* att_dst  = (const float*)d_in[5];
    const float* W_edge   = (const float*)d_in[6];
    const float* att_edge = (const float*)d_in[7];
    const float* bias     = (const float*)d_in[8];
    int N = in_sizes[0] / 2;
    int E = in_sizes[2];
    float* out = (float*)d_out;

    k_edge<<<(E + 511) / 512, 256>>>(ei, ea, x, W, att_src, att_dst, W_edge, att_edge, E, N);
    k_out<<<(N + 63) / 64, 256>>>(W, bias, x, out, N, 1.0f / (float)E);
}

// round 15
// speedup vs baseline: 1.3591x; 1.3591x over previous
#include <cuda_runtime.h>

#define NMAX 50000
#define ACC4 (NMAX * 3)

// ---- scratch (static __device__, zero-initialized at module load) ----
// Invariants at entry of every kernel_launch: g_accum == 0, g_easum == 0, g_done == 0.
__device__ float4   g_accum[ACC4];   // per node: [denom(4)][T0(4)][T1(4)]
__device__ float    g_consts[20];    // s0[4] s1[4] d0[4] d1[4] g[4]
__device__ float    g_easum;
__device__ unsigned g_done;

struct C20 { float s0[4], s1[4], d0[4], d1[4], g[4]; };

// Per-block inline computation of the 20 head constants (shared reduction).
__device__ __forceinline__ void block_consts(const float* __restrict__ W,
                                             const float* __restrict__ att_src,
                                             const float* __restrict__ att_dst,
                                             const float* __restrict__ W_edge,
                                             const float* __restrict__ att_edge,
                                             float* cs /*shared[20]*/) {
    __shared__ float sh[5][256];
    int t = threadIdx.x;          // 256 threads = H*C
    int h = t >> 6;
    float w0 = __ldg(&W[2 * t]), w1 = __ldg(&W[2 * t + 1]);
    float as = __ldg(&att_src[t]), ad = __ldg(&att_dst[t]);
    sh[0][t] = w0 * as;
    sh[1][t] = w1 * as;
    sh[2][t] = w0 * ad;
    sh[3][t] = w1 * ad;
    sh[4][t] = __ldg(&W_edge[t]) * __ldg(&att_edge[t]);
    __syncthreads();
    for (int off = 32; off >= 1; off >>= 1) {
        if ((t & 63) < off) {
            #pragma unroll
            for (int k = 0; k < 5; k++) sh[k][t] += sh[k][t + off];
        }
        __syncthreads();
    }
    if ((t & 63) == 0) {
        #pragma unroll
        for (int k = 0; k < 5; k++) cs[k * 4 + h] = sh[k][t];
    }
    __syncthreads();
}

__device__ __forceinline__ void red_v4(float4* p, float a, float b, float c, float d) {
    asm volatile("red.global.add.v4.f32 [%0], {%1,%2,%3,%4};"
                 :: "l"(p), "f"(a), "f"(b), "f"(c), "f"(d) : "memory");
}

__device__ __forceinline__ void edge_body(const float2* __restrict__ x2,
                                          int src, int dst, float w, int N, const C20& c) {
    if ((unsigned)src >= (unsigned)N || (unsigned)dst >= (unsigned)N) return;
    float2 xs = __ldg(&x2[src]);
    float2 xd = __ldg(&x2[dst]);
    float a0 = xs.x * c.s0[0] + xs.y * c.s1[0] + xd.x * c.d0[0] + xd.y * c.d1[0] + w * c.g[0];
    float a1 = xs.x * c.s0[1] + xs.y * c.s1[1] + xd.x * c.d0[1] + xd.y * c.d1[1] + w * c.g[1];
    float a2 = xs.x * c.s0[2] + xs.y * c.s1[2] + xd.x * c.d0[2] + xd.y * c.d1[2] + w * c.g[2];
    float a3 = xs.x * c.s0[3] + xs.y * c.s1[3] + xd.x * c.d0[3] + xd.y * c.d1[3] + w * c.g[3];
    a0 = fmaxf(a0, 0.2f * a0);
    a1 = fmaxf(a1, 0.2f * a1);
    a2 = fmaxf(a2, 0.2f * a2);
    a3 = fmaxf(a3, 0.2f * a3);
    float e0 = __expf(a0), e1 = __expf(a1), e2 = __expf(a2), e3 = __expf(a3);
    float4* base = &g_accum[dst * 3];
    red_v4(base,     e0,        e1,        e2,        e3);
    red_v4(base + 1, e0 * xs.x, e1 * xs.x, e2 * xs.x, e3 * xs.x);
    red_v4(base + 2, e0 * xs.y, e1 * xs.y, e2 * xs.y, e3 * xs.y);
}

// K1: edge pass (R9 form: 2 edges/thread, scalar streaming loads). UNCHANGED.
__global__ void k_edge(const int* __restrict__ ei, const float* __restrict__ ea,
                       const float* __restrict__ x,
                       const float* __restrict__ W, const float* __restrict__ att_src,
                       const float* __restrict__ att_dst, const float* __restrict__ W_edge,
                       const float* __restrict__ att_edge, int E, int N) {
    __shared__ float cs[20];
    block_consts(W, att_src, att_dst, W_edge, att_edge, cs);
    if (blockIdx.x == 0 && threadIdx.x < 20) g_consts[threadIdx.x] = cs[threadIdx.x];

    C20 c;
    #pragma unroll
    for (int h = 0; h < 4; h++) {
        c.s0[h] = cs[h];      c.s1[h] = cs[4 + h];
        c.d0[h] = cs[8 + h];  c.d1[h] = cs[12 + h];
        c.g[h]  = cs[16 + h];
    }
    const float2* x2 = (const float2*)x;
    int base = blockIdx.x * (blockDim.x * 2) + threadIdx.x;
    int e0 = base, e1 = base + blockDim.x;
    float wsum = 0.f;

    int s0 = 0, d0 = 0, s1 = 0, d1 = 0;
    float w0 = 0.f, w1 = 0.f;
    bool v0 = e0 < E, v1 = e1 < E;
    if (v0) { s0 = __ldcs(&ei[e0]); d0 = __ldcs(&ei[E + e0]); w0 = __ldcs(&ea[e0]); }
    if (v1) { s1 = __ldcs(&ei[e1]); d1 = __ldcs(&ei[E + e1]); w1 = __ldcs(&ea[e1]); }
    if (v0) { wsum += w0; edge_body(x2, s0, d0, w0, N, c); }
    if (v1) { wsum += w1; edge_body(x2, s1, d1, w1, N, c); }

    #pragma unroll
    for (int o = 16; o; o >>= 1) wsum += __shfl_down_sync(0xffffffffu, wsum, o);
    __shared__ float shw[8];
    if ((threadIdx.x & 31) == 0) shw[threadIdx.x >> 5] = wsum;
    __syncthreads();
    if (threadIdx.x == 0) {
        float s = 0.f;
        #pragma unroll
        for (int i = 0; i < 8; i++) s += shw[i];
        atomicAdd(&g_easum, s);
    }
}

// K2: two-phase tiled expansion, TILE=128 (R10 form — best measured k_out).
// Phase A: threads 0..127 reduce one node each -> sh_T; reset accumulators.
// Phase B: simple unrolled loop, LDS.64 + 8 FFMA + STG.128, coalesced.
#define TILE 128
__global__ void k_out(const float* __restrict__ W, const float* __restrict__ bias,
                      const float* __restrict__ x, float* __restrict__ out,
                      int N, float invE) {
    __shared__ float2 sh_T[TILE * 4];   // [local node][head]
    int t = threadIdx.x;
    int base = blockIdx.x * TILE;

    // ---- Phase A ----
    if (t < TILE) {
        int n = base + t;
        if (n < N) {
            float mg = g_easum * invE;
            float2 xn = ((const float2*)x)[n];
            float4 dd4 = __ldcg(&g_accum[n * 3 + 0]);
            float4 t04 = __ldcg(&g_accum[n * 3 + 1]);
            float4 t14 = __ldcg(&g_accum[n * 3 + 2]);
            float4 z = make_float4(0, 0, 0, 0);
            g_accum[n * 3 + 0] = z;
            g_accum[n * 3 + 1] = z;
            g_accum[n * 3 + 2] = z;

            float dd[4] = {dd4.x, dd4.y, dd4.z, dd4.w};
            float t0[4] = {t04.x, t04.y, t04.z, t04.w};
            float t1[4] = {t14.x, t14.y, t14.z, t14.w};
            #pragma unroll
            for (int h = 0; h < 4; h++) {
                float c0 = g_consts[h] + g_consts[8 + h];
                float c1 = g_consts[4 + h] + g_consts[12 + h];
                float a = xn.x * c0 + xn.y * c1 + mg * g_consts[16 + h];
                a = fmaxf(a, 0.2f * a);
                float ws = __expf(a);
                float r = 1.0f / (dd[h] + ws);
                sh_T[t * 4 + h] = make_float2((t0[h] + ws * xn.x) * r,
                                              (t1[h] + ws * xn.y) * r);
            }
        }
    }

    // ---- Phase B setup (all threads; independent of phase A) ----
    int row = t >> 6;        // 0..3
    int sub = t & 63;        // output float4 column
    int h = sub >> 4;        // head for these 4 columns
    const float4* W4 = (const float4*)W;
    float4 wa = __ldg(&W4[sub * 2]);
    float4 wb = __ldg(&W4[sub * 2 + 1]);
    float4 b4 = __ldg(&((const float4*)bias)[sub]);

    __syncthreads();

    float4* o4 = (float4*)out;
    if (base + TILE <= N) {
        // full tile, no guards
        #pragma unroll 8
        for (int i = 0; i < TILE / 4; i++) {
            int ln = i * 4 + row;
            float2 T = sh_T[ln * 4 + h];
            float4 o;
            o.x = T.x * wa.x + T.y * wa.y + b4.x;
            o.y = T.x * wa.z + T.y * wa.w + b4.y;
            o.z = T.x * wb.x + T.y * wb.y + b4.z;
            o.w = T.x * wb.z + T.y * wb.w + b4.w;
            __stcs(&o4[(size_t)(base + ln) * 64 + sub], o);
        }
    } else {
        for (int i = 0; i < TILE / 4; i++) {
            int ln = i * 4 + row;
            int n = base + ln;
            if (n >= N) break;
            float2 T = sh_T[ln * 4 + h];
            float4 o;
            o.x = T.x * wa.x + T.y * wa.y + b4.x;
            o.y = T.x * wa.z + T.y * wa.w + b4.y;
            o.z = T.x * wb.x + T.y * wb.y + b4.z;
            o.w = T.x * wb.z + T.y * wb.w + b4.w;
            __stcs(&o4[(size_t)n * 64 + sub], o);
        }
    }

    // last block resets g_easum for the next replay (every block already read it)
    __syncthreads();
    if (t == 0) {
        unsigned v = atomicInc(&g_done, gridDim.x - 1);   // wraps to 0 on last block
        if (v == gridDim.x - 1) g_easum = 0.f;
    }
}

extern "C" void kernel_launch(void* const* d_in, const int* in_sizes, int n_in,
                              void* d_out, int out_size) {
    const float* x        = (const float*)d_in[0];
    const int*   ei       = (const int*)d_in[1];     // int32 (JAX x64 off)
    const float* ea       = (const float*)d_in[2];
    const float* W        = (const float*)d_in[3];
    const float* att_src  = (const float*)d_in[4];
    const float* att_dst  = (const float*)d_in[5];
    const float* W_edge   = (const float*)d_in[6];
    const float* att_edge = (const float*)d_in[7];
    const float* bias     = (const float*)d_in[8];
    int N = in_sizes[0] / 2;
    int E = in_sizes[2];
    float* out = (float*)d_out;

    k_edge<<<(E + 511) / 512, 256>>>(ei, ea, x, W, att_src, att_dst, W_edge, att_edge, E, N);
    k_out<<<(N + TILE - 1) / TILE, 256>>>(W, bias, x, out, N, 1.0f / (float)E);
}